// round 8
// baseline (speedup 1.0000x reference)
#include <cuda_runtime.h>
#include <math.h>
#include <stdint.h>

#define NN 768
#define HH 12
#define CS 384
#define PROJ_N 1152
#define FEAT_N 2112   // [o 192 | ptx 96 | pty 96 | ptz 96 | ptnorm 96 | opair 1536]

typedef unsigned long long ull;

#define S1 0.14433756729740643f      // sqrt(1/48)
#define SQ13 0.5773502691896258f     // sqrt(1/3)
#define HWF 0.13608276348795434f     // sqrt(1/54)

__device__ __forceinline__ void ffma2(ull& d, ull a, ull b) {
    asm("fma.rn.f32x2 %0, %1, %2, %0;" : "+l"(d) : "l"(a), "l"(b));
}
__device__ __forceinline__ ull fadd2(ull a, ull b) {
    ull r; asm("add.rn.f32x2 %0, %1, %2;" : "=l"(r) : "l"(a), "l"(b)); return r;
}
__device__ __forceinline__ ull pack2(float x, float y) {
    ull r; asm("mov.b64 %0, {%1, %2};" : "=l"(r) : "f"(x), "f"(y)); return r;
}
__device__ __forceinline__ float2 unpack2(ull v) {
    float2 r; asm("mov.b64 {%0, %1}, %2;" : "=f"(r.x), "=f"(r.y) : "l"(v)); return r;
}

// ---------------- scratch ----------------
__device__ float g_proj[NN * PROJ_N];
__device__ float g_v[NN * 192];
__device__ float g_vpts[NN * 288];
__device__ float g_qb[HH * NN * 32];
__device__ float g_kb[HH * NN * 32];
__device__ float g_qkp[(size_t)NN * HH * NN]; // [i][h][j]
__device__ float g_bias[(size_t)NN * NN * HH];// [i][j][h] = SQ13*(z@w_b + b_b)
__device__ float g_a[(size_t)NN * HH * NN];   // [i][h][j]
__device__ float g_aT[(size_t)NN * NN * HH];  // [i][j][h]
__device__ float g_optg[NN * 288];
__device__ float g_feats[NN * FEAT_N];

// ---------------- GEMM: out = A @ W + bias, segmented over N ----------------
__global__ __launch_bounds__(256) void gemm_kernel(
    const float* __restrict__ A, int K,
    const float* __restrict__ w0, const float* __restrict__ w1,
    const float* __restrict__ w2, const float* __restrict__ w3,
    const float* __restrict__ b0, const float* __restrict__ b1,
    const float* __restrict__ b2, const float* __restrict__ b3,
    int e0, int e1, int e2, int e3,
    float* __restrict__ out, int ldo)
{
    __shared__ float As[16][34];
    __shared__ float Bs[16][64];

    const int m0 = blockIdx.y * 32;
    const int n0 = blockIdx.x * 64;
    const int t = threadIdx.x;

    const int bkr = t >> 4;
    const int n   = n0 + (t & 15) * 4;
    const float* W; const float* bias; int base, segN;
    if (n < e0)      { W = w0; bias = b0; base = 0;  segN = e0; }
    else if (n < e1) { W = w1; bias = b1; base = e0; segN = e1 - e0; }
    else if (n < e2) { W = w2; bias = b2; base = e1; segN = e2 - e1; }
    else             { W = w3; bias = b3; base = e2; segN = e3 - e2; }

    const int ar  = t >> 2;
    const int ac4 = (t & 3) * 4;
    const int ty  = t >> 4;
    const int tx  = t & 15;

    float acc[2][4] = {};

    for (int k0 = 0; k0 < K; k0 += 16) {
        if (t < 128) {
            float4 av = *(const float4*)&A[(size_t)(m0 + ar) * K + k0 + ac4];
            As[ac4 + 0][ar] = av.x; As[ac4 + 1][ar] = av.y;
            As[ac4 + 2][ar] = av.z; As[ac4 + 3][ar] = av.w;
        }
        float4 bv = *(const float4*)&W[(size_t)(k0 + bkr) * segN + (n - base)];
        *(float4*)&Bs[bkr][(t & 15) * 4] = bv;
        __syncthreads();
        #pragma unroll
        for (int kk = 0; kk < 16; kk++) {
            float2 a2 = *(const float2*)&As[kk][ty * 2];
            float4 b4 = *(const float4*)&Bs[kk][tx * 4];
            acc[0][0] += a2.x * b4.x; acc[0][1] += a2.x * b4.y;
            acc[0][2] += a2.x * b4.z; acc[0][3] += a2.x * b4.w;
            acc[1][0] += a2.y * b4.x; acc[1][1] += a2.y * b4.y;
            acc[1][2] += a2.y * b4.z; acc[1][3] += a2.y * b4.w;
        }
        __syncthreads();
    }
    float4 bb = *(const float4*)&bias[n - base];
    #pragma unroll
    for (int r = 0; r < 2; r++) {
        float4 o;
        o.x = acc[r][0] + bb.x; o.y = acc[r][1] + bb.y;
        o.z = acc[r][2] + bb.z; o.w = acc[r][3] + bb.w;
        *(float4*)&out[(size_t)(m0 + ty * 2 + r) * ldo + n] = o;
    }
}

// ---------------- prep ----------------
__global__ __launch_bounds__(384) void prep_kernel(
    const float* __restrict__ rot, const float* __restrict__ trans,
    const float* __restrict__ head_w)
{
    __shared__ float s_qp3[144];
    __shared__ float s_kp3[144];

    const int n = blockIdx.x;
    const int t = threadIdx.x;
    const float* pr = &g_proj[(size_t)n * PROJ_N];

    if (t < 192) {
        int h = t >> 4, c = t & 15;
        g_kb[((size_t)h * NN + n) * 32 + c] = pr[192 + h * 32 + c];
        g_v[n * 192 + t] = pr[192 + h * 32 + 16 + c];
    }
    float r[9], tr[3];
    #pragma unroll
    for (int e = 0; e < 9; e++) r[e] = rot[n * 9 + e];
    tr[0] = trans[n * 3 + 0]; tr[1] = trans[n * 3 + 1]; tr[2] = trans[n * 3 + 2];

    if (t < 48) {
        float p0 = pr[576 + 0 * 48 + t];
        float p1 = pr[576 + 1 * 48 + t];
        float p2 = pr[576 + 2 * 48 + t];
        #pragma unroll
        for (int ii = 0; ii < 3; ii++)
            s_qp3[t * 3 + ii] = r[ii * 3 + 0] * p0 + r[ii * 3 + 1] * p1 + r[ii * 3 + 2] * p2 + tr[ii];
    }
    if (t >= 64 && t < 208) {
        int u = t - 64;
        float p0 = pr[720 + 0 * 144 + u];
        float p1 = pr[720 + 1 * 144 + u];
        float p2 = pr[720 + 2 * 144 + u];
        int h = u / 12, p = u % 12;
        #pragma unroll
        for (int ii = 0; ii < 3; ii++) {
            float o = r[ii * 3 + 0] * p0 + r[ii * 3 + 1] * p1 + r[ii * 3 + 2] * p2 + tr[ii];
            if (p < 4) s_kp3[(h * 4 + p) * 3 + ii] = o;
            else       g_vpts[n * 288 + (h * 8 + (p - 4)) * 3 + ii] = o;
        }
    }
    __syncthreads();

    {
        int h = t >> 5, e = t & 31;
        float x = head_w[h];
        float hw = ((x > 20.f) ? x : log1pf(__expf(x))) * HWF;

        float qv;
        if (e < 16)       qv = pr[h * 16 + e] * S1;
        else if (e < 28)  qv = s_qp3[h * 12 + (e - 16)] * hw;
        else if (e == 28) qv = -0.5f * hw;
        else if (e == 29) {
            float nq = 0.f;
            #pragma unroll
            for (int d = 0; d < 12; d++) { float v = s_qp3[h * 12 + d]; nq += v * v; }
            qv = -0.5f * hw * nq;
        } else qv = 0.f;
        g_qb[((size_t)h * NN + n) * 32 + e] = qv;

        if (e >= 16) {
            float kv2;
            if (e < 28)       kv2 = s_kp3[h * 12 + (e - 16)];
            else if (e == 28) {
                float nk = 0.f;
                #pragma unroll
                for (int d = 0; d < 12; d++) { float v = s_kp3[h * 12 + d]; nk += v * v; }
                kv2 = nk;
            }
            else if (e == 29) kv2 = 1.f;
            else              kv2 = 0.f;
            g_kb[((size_t)h * NN + n) * 32 + e] = kv2;
        }
    }
}

// ---------------- qkpts ----------------
__global__ __launch_bounds__(256) void qkpts_kernel(const float* __restrict__ mask)
{
    __shared__ float As[32][68];
    __shared__ float Bs[32][68];
    __shared__ float s_mi[64], s_mj[64];

    const int i0 = blockIdx.x * 64;
    const int j0 = blockIdx.y * 64;
    const int h  = blockIdx.z;
    const int t = threadIdx.x;

    #pragma unroll
    for (int r2 = 0; r2 < 2; r2++) {
        int li = t + r2 * 256;
        int row = li >> 3, c4 = (li & 7) * 4;
        float4 a = *(const float4*)&g_qb[((size_t)h * NN + i0 + row) * 32 + c4];
        As[c4 + 0][row] = a.x; As[c4 + 1][row] = a.y;
        As[c4 + 2][row] = a.z; As[c4 + 3][row] = a.w;
        float4 b = *(const float4*)&g_kb[((size_t)h * NN + j0 + row) * 32 + c4];
        Bs[c4 + 0][row] = b.x; Bs[c4 + 1][row] = b.y;
        Bs[c4 + 2][row] = b.z; Bs[c4 + 3][row] = b.w;
    }
    if (t < 64)              s_mi[t] = mask[i0 + t];
    else if (t < 128)        s_mj[t - 64] = mask[j0 + t - 64];
    __syncthreads();

    const int ty = t >> 4, tx = t & 15;
    float acc[4][4] = {};
    #pragma unroll
    for (int k = 0; k < 32; k++) {
        float4 a4 = *(const float4*)&As[k][ty * 4];
        float4 b4 = *(const float4*)&Bs[k][tx * 4];
        acc[0][0] += a4.x * b4.x; acc[0][1] += a4.x * b4.y; acc[0][2] += a4.x * b4.z; acc[0][3] += a4.x * b4.w;
        acc[1][0] += a4.y * b4.x; acc[1][1] += a4.y * b4.y; acc[1][2] += a4.y * b4.z; acc[1][3] += a4.y * b4.w;
        acc[2][0] += a4.z * b4.x; acc[2][1] += a4.z * b4.y; acc[2][2] += a4.z * b4.z; acc[2][3] += a4.z * b4.w;
        acc[3][0] += a4.w * b4.x; acc[3][1] += a4.w * b4.y; acc[3][2] += a4.w * b4.z; acc[3][3] += a4.w * b4.w;
    }
    #pragma unroll
    for (int rr = 0; rr < 4; rr++) {
        float mi = s_mi[ty * 4 + rr];
        float4 o;
        o.x = acc[rr][0] + 100000.f * (mi * s_mj[tx * 4 + 0] - 1.f);
        o.y = acc[rr][1] + 100000.f * (mi * s_mj[tx * 4 + 1] - 1.f);
        o.z = acc[rr][2] + 100000.f * (mi * s_mj[tx * 4 + 2] - 1.f);
        o.w = acc[rr][3] + 100000.f * (mi * s_mj[tx * 4 + 3] - 1.f);
        *(float4*)&g_qkp[(size_t)(i0 + ty * 4 + rr) * 9216 + h * 768 + j0 + tx * 4] = o;
    }
}

// ---------------- bias: g_bias[row][h] = SQ13*(z[row]@w_b + b_b), warp per row-pair ----------------
// Lanes: l16 = c-chunk (8 c each), hi/lo half-warp = heads 0-5 / 6-11. w_b in registers.
#define NROWPAIRS (NN * NN / 2)
__global__ __launch_bounds__(256) void bias_kernel(
    const float* __restrict__ z, const float* __restrict__ w_b,
    const float* __restrict__ b_b)
{
    const int t = threadIdx.x;
    const int lane = t & 31;
    const int l16 = lane & 15;
    const int hb = (lane >> 4) * 6;

    // w regs: wreg[k][q] = (w_b[c][hb+2q], w_b[c][hb+2q+1]), c = l16*8+k
    ull wreg[8][3];
    #pragma unroll
    for (int k = 0; k < 8; k++) {
        const float* wp = w_b + (l16 * 8 + k) * 12 + hb;
        #pragma unroll
        for (int q = 0; q < 3; q++)
            wreg[k][q] = pack2(wp[2 * q], wp[2 * q + 1]);
    }
    float bbv[6];
    #pragma unroll
    for (int m = 0; m < 6; m++) bbv[m] = b_b[hb + m];

    const int gw = (blockIdx.x * 256 + t) >> 5;
    const int nwarp = gridDim.x * 8;

    for (int rp = gw; rp < NROWPAIRS; rp += nwarp) {
        const size_t row = (size_t)rp * 2;
        const float* zr = z + row * 128 + l16 * 8;
        float4 za0 = __ldg((const float4*)(zr));
        float4 zb0 = __ldg((const float4*)(zr + 4));
        float4 za1 = __ldg((const float4*)(zr + 128));
        float4 zb1 = __ldg((const float4*)(zr + 132));

        ull acc0[3] = {0ull, 0ull, 0ull}, acc1[3] = {0ull, 0ull, 0ull};
        float c0[8] = {za0.x, za0.y, za0.z, za0.w, zb0.x, zb0.y, zb0.z, zb0.w};
        float c1[8] = {za1.x, za1.y, za1.z, za1.w, zb1.x, zb1.y, zb1.z, zb1.w};
        #pragma unroll
        for (int k = 0; k < 8; k++) {
            ull z0 = pack2(c0[k], c0[k]);
            ull z1 = pack2(c1[k], c1[k]);
            #pragma unroll
            for (int q = 0; q < 3; q++) {
                ffma2(acc0[q], z0, wreg[k][q]);
                ffma2(acc1[q], z1, wreg[k][q]);
            }
        }
        // reduce over 16 lanes (xor < 16 keeps half-warp groups separate)
        #pragma unroll
        for (int s = 1; s < 16; s <<= 1) {
            #pragma unroll
            for (int q = 0; q < 3; q++) {
                acc0[q] = fadd2(acc0[q], __shfl_xor_sync(0xffffffffu, acc0[q], s));
                acc1[q] = fadd2(acc1[q], __shfl_xor_sync(0xffffffffu, acc1[q], s));
            }
        }
        if (l16 == 0) {
            #pragma unroll
            for (int q = 0; q < 3; q++) {
                float2 u0 = unpack2(acc0[q]);
                float2 u1 = unpack2(acc1[q]);
                float2 o0, o1;
                o0.x = SQ13 * (u0.x + bbv[2 * q]);     o0.y = SQ13 * (u0.y + bbv[2 * q + 1]);
                o1.x = SQ13 * (u1.x + bbv[2 * q]);     o1.y = SQ13 * (u1.y + bbv[2 * q + 1]);
                *(float2*)&g_bias[row * 12 + hb + 2 * q] = o0;
                *(float2*)&g_bias[(row + 1) * 12 + hb + 2 * q] = o1;
            }
        }
    }
}

// ---------------- softmax: logits = qkp + bias; softmax per head; write a / aT ----------------
#define LP 772
__global__ __launch_bounds__(256) void softmax_kernel(const float* __restrict__ ss)
{
    __shared__ float s_l[12 * LP];
    __shared__ float s_w[768];

    const int i = blockIdx.x;
    const int t = threadIdx.x;

    // stage bias transposed: [j][h] -> s_l[h][j]
    for (int idx = t; idx < 9216; idx += 256) {
        int j = idx / 12, h = idx - j * 12;
        s_l[h * LP + j] = g_bias[(size_t)i * 9216 + idx];
    }
    for (int idx = t; idx < 768; idx += 256)
        s_w[idx] = __expf(ss[(size_t)i * 768 + idx]) - 0.99f;
    __syncthreads();
    // add qkp ([h][j] layout, coalesced)
    for (int idx = t; idx < 9216; idx += 256) {
        int h = idx / 768, j = idx - h * 768;
        s_l[h * LP + j] += g_qkp[(size_t)i * 9216 + idx];
    }
    __syncthreads();

    const int wrp = t >> 5, lane = t & 31;
    for (int h = wrp; h < 12; h += 8) {
        float* lr = &s_l[h * LP];
        float m = -1e30f;
        for (int j = lane; j < 768; j += 32) m = fmaxf(m, lr[j]);
        #pragma unroll
        for (int o = 16; o; o >>= 1) m = fmaxf(m, __shfl_xor_sync(0xffffffffu, m, o));
        float sum = 0.f;
        for (int j = lane; j < 768; j += 32) {
            float p = __expf(lr[j] - m) * s_w[j];
            lr[j] = p;
            sum += p;
        }
        #pragma unroll
        for (int o = 16; o; o >>= 1) sum += __shfl_xor_sync(0xffffffffu, sum, o);
        float inv = 1.f / sum;
        for (int j = lane; j < 768; j += 32) lr[j] *= inv;
    }
    __syncthreads();

    for (int idx = t; idx < 9216; idx += 256) {
        int h = idx / 768, j = idx - h * 768;
        g_a[(size_t)i * 9216 + idx] = s_l[h * LP + j];
    }
    for (int idx = t; idx < 9216; idx += 256) {
        int j = idx / 12, h = idx - j * 12;
        g_aT[(size_t)i * 9216 + idx] = s_l[h * LP + j];
    }
}

// ---------------- opair: o_pair[i][h][c] = sum_j a[i][j][h]*z[i][j][c], MLP-4 ----------------
#define OP_SMEM_FLOATS (9216 + 4 * 12 * 128)
__global__ __launch_bounds__(128) void opair_kernel(const float* __restrict__ z)
{
    extern __shared__ float smop[];
    float* s_a    = smop;          // [j][12]
    float* s_part = smop + 9216;   // [w][12][128]

    const int i = blockIdx.x;
    const int t = threadIdx.x;
    const int w = t >> 5, lane = t & 31;

    for (int idx = t; idx < 2304; idx += 128)
        *(float4*)&s_a[idx * 4] = *(const float4*)&g_aT[(size_t)i * 9216 + idx * 4];
    __syncthreads();

    // acc[q][c]: head-pair (2q, 2q+1) for column lane*4+c
    ull acc[6][4];
    #pragma unroll
    for (int q = 0; q < 6; q++)
        #pragma unroll
        for (int c = 0; c < 4; c++) acc[q][c] = 0ull;

    const float* zb = z + (size_t)i * 768 * 128 + lane * 4;
    for (int jb = w * 4; jb < 768; jb += 16) {
        float4 zv[4];
        #pragma unroll
        for (int u = 0; u < 4; u++)
            zv[u] = __ldg((const float4*)(zb + (size_t)(jb + u) * 128));
        #pragma unroll
        for (int u = 0; u < 4; u++) {
            const ull* ap = (const ull*)&s_a[(jb + u) * 12];   // 6 head-pairs (LDS.64 broadcast)
            float zc[4] = {zv[u].x, zv[u].y, zv[u].z, zv[u].w};
            #pragma unroll
            for (int c = 0; c < 4; c++) {
                ull zz = pack2(zc[c], zc[c]);
                #pragma unroll
                for (int q = 0; q < 6; q++)
                    ffma2(acc[q][c], ap[q], zz);
            }
        }
    }

    #pragma unroll
    for (int q = 0; q < 6; q++) {
        #pragma unroll
        for (int c = 0; c < 4; c++) {
            float2 u = unpack2(acc[q][c]);
            s_part[(w * 12 + 2 * q + 0) * 128 + lane * 4 + c] = u.x;
            s_part[(w * 12 + 2 * q + 1) * 128 + lane * 4 + c] = u.y;
        }
    }
    __syncthreads();

    for (int idx = t; idx < 1536; idx += 128) {
        int h = idx >> 7, c = idx & 127;
        float s = s_part[(0 * 12 + h) * 128 + c] + s_part[(1 * 12 + h) * 128 + c]
                + s_part[(2 * 12 + h) * 128 + c] + s_part[(3 * 12 + h) * 128 + c];
        g_feats[(size_t)i * FEAT_N + 576 + h * 128 + c] = s;
    }
}

// ---------------- ov: 32-row tiles, 128 threads, grid (24,12) ----------------
__global__ __launch_bounds__(128) void ov_kernel()
{
    __shared__ float s_a[32 * 64];
    __shared__ float s_v[64 * 40];

    const int i0 = blockIdx.x * 32;
    const int h  = blockIdx.y;
    const int t = threadIdx.x;
    const int ig = t >> 3;    // 0..15 -> 2 rows
    const int og = t & 7;     // 5 outputs

    float acc[2][5] = {};

    for (int j0 = 0; j0 < 768; j0 += 64) {
        #pragma unroll
        for (int it = 0; it < 4; it++) {
            int idx = t + it * 128;
            int row = idx >> 4, q = idx & 15;
            float4 av = *(const float4*)&g_a[((size_t)(i0 + row) * 12 + h) * 768 + j0 + q * 4];
            *(float4*)&s_a[row * 64 + q * 4] = av;
        }
        #pragma unroll
        for (int it = 0; it < 5; it++) {
            int idx = t + it * 128;           // 640 float4 slots
            int jj = idx / 10, q = idx - jj * 10;
            float4 vv = (q < 4)
                ? *(const float4*)&g_v[(j0 + jj) * 192 + h * 16 + q * 4]
                : *(const float4*)&g_vpts[(j0 + jj) * 288 + h * 24 + (q - 4) * 4];
            *(float4*)&s_v[jj * 40 + q * 4] = vv;
        }
        __syncthreads();
        #pragma unroll 8
        for (int jj = 0; jj < 64; jj++) {
            float a0 = s_a[(ig * 2 + 0) * 64 + jj];
            float a1 = s_a[(ig * 2 + 1) * 64 + jj];
            const float* vp = &s_v[jj * 40 + og * 5];
            #pragma unroll
            for (int u = 0; u < 5; u++) {
                float vv = vp[u];
                acc[0][u] += a0 * vv;
                acc[1][u] += a1 * vv;
            }
        }
        __syncthreads();
    }
    #pragma unroll
    for (int r = 0; r < 2; r++) {
        int n = i0 + ig * 2 + r;
        #pragma unroll
        for (int u = 0; u < 5; u++) {
            int e = og * 5 + u;
            if (e < 16) g_feats[(size_t)n * FEAT_N + h * 16 + e] = acc[r][u];
            else        g_optg[n * 288 + h * 24 + (e - 16)] = acc[r][u];
        }
    }
}

// ---------------- optfinal ----------------
__global__ __launch_bounds__(96) void optfinal_kernel(
    const float* __restrict__ rot, const float* __restrict__ trans)
{
    const int n = blockIdx.x;
    const int hp = threadIdx.x;
    float r[9], tr[3];
    #pragma unroll
    for (int e = 0; e < 9; e++) r[e] = rot[n * 9 + e];
    tr[0] = trans[n * 3 + 0]; tr[1] = trans[n * 3 + 1]; tr[2] = trans[n * 3 + 2];

    float gx = g_optg[n * 288 + hp * 3 + 0] - tr[0];
    float gy = g_optg[n * 288 + hp * 3 + 1] - tr[1];
    float gz = g_optg[n * 288 + hp * 3 + 2] - tr[2];
    float l0 = r[0] * gx + r[3] * gy + r[6] * gz;
    float l1 = r[1] * gx + r[4] * gy + r[7] * gz;
    float l2 = r[2] * gx + r[5] * gy + r[8] * gz;

    float* f = &g_feats[(size_t)n * FEAT_N];
    f[192 + hp] = l0;
    f[288 + hp] = l1;
    f[384 + hp] = l2;
    f[480 + hp] = sqrtf(l0 * l0 + l1 * l1 + l2 * l2 + 1e-8f);
}

// ---------------- launch ----------------
extern "C" void kernel_launch(void* const* d_in, const int* in_sizes, int n_in,
                              void* d_out, int out_size)
{
    const float* s       = (const float*)d_in[0];
    const float* z       = (const float*)d_in[1];
    const float* rot     = (const float*)d_in[2];
    const float* trans   = (const float*)d_in[3];
    const float* mask    = (const float*)d_in[4];
    const float* ss      = (const float*)d_in[5];
    const float* w_q     = (const float*)d_in[6];
    const float* b_q     = (const float*)d_in[7];
    const float* w_kv    = (const float*)d_in[8];
    const float* b_kv    = (const float*)d_in[9];
    const float* w_qp    = (const float*)d_in[10];
    const float* b_qp    = (const float*)d_in[11];
    const float* w_kvp   = (const float*)d_in[12];
    const float* b_kvp   = (const float*)d_in[13];
    const float* w_b     = (const float*)d_in[14];
    const float* b_b     = (const float*)d_in[15];
    const float* head_w  = (const float*)d_in[16];
    const float* w_out   = (const float*)d_in[17];
    const float* b_out   = (const float*)d_in[18];
    float* out = (float*)d_out;

    float* proj;  cudaGetSymbolAddress((void**)&proj, g_proj);
    float* feats; cudaGetSymbolAddress((void**)&feats, g_feats);

    static bool attr_done = false;
    if (!attr_done) {
        cudaFuncSetAttribute(opair_kernel,
                             cudaFuncAttributeMaxDynamicSharedMemorySize,
                             OP_SMEM_FLOATS * 4);
        attr_done = true;
    }

    // K1: projections (768 x 1152)
    gemm_kernel<<<dim3(18, 24), 256>>>(
        s, CS, w_q, w_kv, w_qp, w_kvp, b_q, b_kv, b_qp, b_kvp,
        192, 576, 720, 1152, proj, PROJ_N);

    // K2: split k/v, rotate points, build logit-GEMM rows
    prep_kernel<<<NN, 384>>>(rot, trans, head_w);

    // K2b: qk+pts+mask logits as 30-dim GEMM
    qkpts_kernel<<<dim3(12, 12, 12), 256>>>(mask);

    // K3a: z-bias GEMM, warp-per-row-pair, w in registers (z pass 1)
    bias_kernel<<<296, 256>>>(z, w_b, b_b);

    // K3b: softmax
    softmax_kernel<<<NN, 256>>>(ss);

    // K3c: o_pair (z pass 2, MLP-4)
    opair_kernel<<<NN, 128, OP_SMEM_FLOATS * 4>>>(z);

    // K4: o and o_pt accumulation
    ov_kernel<<<dim3(24, 12), 128>>>();

    // K5: finalize o_pt + norms
    optfinal_kernel<<<NN, 96>>>(rot, trans);

    // K6: output GEMM (768 x 384, K=2112)
    gemm_kernel<<<dim3(6, 24), 256>>>(
        feats, FEAT_N, w_out, w_out, w_out, w_out, b_out, b_out, b_out, b_out,
        384, 384, 384, 384, out, CS);
}

// round 9
// speedup vs baseline: 1.1575x; 1.1575x over previous
#include <cuda_runtime.h>
#include <math.h>
#include <stdint.h>

#define NN 768
#define HH 12
#define CS 384
#define PROJ_N 1152
#define FEAT_N 2112   // [o 192 | ptx 96 | pty 96 | ptz 96 | ptnorm 96 | opair 1536]

typedef unsigned long long ull;

#define S1 0.14433756729740643f      // sqrt(1/48)
#define SQ13 0.5773502691896258f     // sqrt(1/3)
#define HWF 0.13608276348795434f     // sqrt(1/54)

__device__ __forceinline__ void ffma2(ull& d, ull a, ull b) {
    asm("fma.rn.f32x2 %0, %1, %2, %0;" : "+l"(d) : "l"(a), "l"(b));
}
__device__ __forceinline__ ull pack2(float x, float y) {
    ull r; asm("mov.b64 %0, {%1, %2};" : "=l"(r) : "f"(x), "f"(y)); return r;
}
__device__ __forceinline__ float2 unpack2(ull v) {
    float2 r; asm("mov.b64 {%0, %1}, %2;" : "=f"(r.x), "=f"(r.y) : "l"(v)); return r;
}
__device__ __forceinline__ uint32_t to_tf32(float f) {
    uint32_t r; asm("cvt.rna.tf32.f32 %0, %1;" : "=r"(r) : "f"(f)); return r;
}
__device__ __forceinline__ void mma_tf32(float c[4],
    uint32_t a0, uint32_t a1, uint32_t a2, uint32_t a3,
    uint32_t b0, uint32_t b1)
{
    asm("mma.sync.aligned.m16n8k8.row.col.f32.tf32.tf32.f32 "
        "{%0,%1,%2,%3}, {%4,%5,%6,%7}, {%8,%9}, {%0,%1,%2,%3};"
        : "+f"(c[0]), "+f"(c[1]), "+f"(c[2]), "+f"(c[3])
        : "r"(a0), "r"(a1), "r"(a2), "r"(a3), "r"(b0), "r"(b1));
}

// ---------------- scratch ----------------
__device__ float g_proj[NN * PROJ_N];
__device__ float g_v[NN * 192];
__device__ float g_vpts[NN * 288];
__device__ float g_qb[HH * NN * 32];
__device__ float g_kb[HH * NN * 32];
__device__ float g_qkp[(size_t)NN * HH * NN]; // [i][h][j]
__device__ float g_bias[(size_t)NN * NN * HH];// [i][j][h] = SQ13*(z@w_b + b_b)
__device__ float g_a[(size_t)NN * HH * NN];   // [i][h][j]
__device__ float g_aT[(size_t)NN * NN * HH];  // [i][j][h]
__device__ float g_optg[NN * 288];
__device__ float g_feats[NN * FEAT_N];

// ---------------- GEMM: out = A @ W + bias, segmented over N ----------------
__global__ __launch_bounds__(256) void gemm_kernel(
    const float* __restrict__ A, int K,
    const float* __restrict__ w0, const float* __restrict__ w1,
    const float* __restrict__ w2, const float* __restrict__ w3,
    const float* __restrict__ b0, const float* __restrict__ b1,
    const float* __restrict__ b2, const float* __restrict__ b3,
    int e0, int e1, int e2, int e3,
    float* __restrict__ out, int ldo)
{
    __shared__ float As[16][34];
    __shared__ float Bs[16][64];

    const int m0 = blockIdx.y * 32;
    const int n0 = blockIdx.x * 64;
    const int t = threadIdx.x;

    const int bkr = t >> 4;
    const int n   = n0 + (t & 15) * 4;
    const float* W; const float* bias; int base, segN;
    if (n < e0)      { W = w0; bias = b0; base = 0;  segN = e0; }
    else if (n < e1) { W = w1; bias = b1; base = e0; segN = e1 - e0; }
    else if (n < e2) { W = w2; bias = b2; base = e1; segN = e2 - e1; }
    else             { W = w3; bias = b3; base = e2; segN = e3 - e2; }

    const int ar  = t >> 2;
    const int ac4 = (t & 3) * 4;
    const int ty  = t >> 4;
    const int tx  = t & 15;

    float acc[2][4] = {};

    for (int k0 = 0; k0 < K; k0 += 16) {
        if (t < 128) {
            float4 av = *(const float4*)&A[(size_t)(m0 + ar) * K + k0 + ac4];
            As[ac4 + 0][ar] = av.x; As[ac4 + 1][ar] = av.y;
            As[ac4 + 2][ar] = av.z; As[ac4 + 3][ar] = av.w;
        }
        float4 bv = *(const float4*)&W[(size_t)(k0 + bkr) * segN + (n - base)];
        *(float4*)&Bs[bkr][(t & 15) * 4] = bv;
        __syncthreads();
        #pragma unroll
        for (int kk = 0; kk < 16; kk++) {
            float2 a2 = *(const float2*)&As[kk][ty * 2];
            float4 b4 = *(const float4*)&Bs[kk][tx * 4];
            acc[0][0] += a2.x * b4.x; acc[0][1] += a2.x * b4.y;
            acc[0][2] += a2.x * b4.z; acc[0][3] += a2.x * b4.w;
            acc[1][0] += a2.y * b4.x; acc[1][1] += a2.y * b4.y;
            acc[1][2] += a2.y * b4.z; acc[1][3] += a2.y * b4.w;
        }
        __syncthreads();
    }
    float4 bb = *(const float4*)&bias[n - base];
    #pragma unroll
    for (int r = 0; r < 2; r++) {
        float4 o;
        o.x = acc[r][0] + bb.x; o.y = acc[r][1] + bb.y;
        o.z = acc[r][2] + bb.z; o.w = acc[r][3] + bb.w;
        *(float4*)&out[(size_t)(m0 + ty * 2 + r) * ldo + n] = o;
    }
}

// ---------------- prep ----------------
__global__ __launch_bounds__(384) void prep_kernel(
    const float* __restrict__ rot, const float* __restrict__ trans,
    const float* __restrict__ head_w)
{
    __shared__ float s_qp3[144];
    __shared__ float s_kp3[144];

    const int n = blockIdx.x;
    const int t = threadIdx.x;
    const float* pr = &g_proj[(size_t)n * PROJ_N];

    if (t < 192) {
        int h = t >> 4, c = t & 15;
        g_kb[((size_t)h * NN + n) * 32 + c] = pr[192 + h * 32 + c];
        g_v[n * 192 + t] = pr[192 + h * 32 + 16 + c];
    }
    float r[9], tr[3];
    #pragma unroll
    for (int e = 0; e < 9; e++) r[e] = rot[n * 9 + e];
    tr[0] = trans[n * 3 + 0]; tr[1] = trans[n * 3 + 1]; tr[2] = trans[n * 3 + 2];

    if (t < 48) {
        float p0 = pr[576 + 0 * 48 + t];
        float p1 = pr[576 + 1 * 48 + t];
        float p2 = pr[576 + 2 * 48 + t];
        #pragma unroll
        for (int ii = 0; ii < 3; ii++)
            s_qp3[t * 3 + ii] = r[ii * 3 + 0] * p0 + r[ii * 3 + 1] * p1 + r[ii * 3 + 2] * p2 + tr[ii];
    }
    if (t >= 64 && t < 208) {
        int u = t - 64;
        float p0 = pr[720 + 0 * 144 + u];
        float p1 = pr[720 + 1 * 144 + u];
        float p2 = pr[720 + 2 * 144 + u];
        int h = u / 12, p = u % 12;
        #pragma unroll
        for (int ii = 0; ii < 3; ii++) {
            float o = r[ii * 3 + 0] * p0 + r[ii * 3 + 1] * p1 + r[ii * 3 + 2] * p2 + tr[ii];
            if (p < 4) s_kp3[(h * 4 + p) * 3 + ii] = o;
            else       g_vpts[n * 288 + (h * 8 + (p - 4)) * 3 + ii] = o;
        }
    }
    __syncthreads();

    {
        int h = t >> 5, e = t & 31;
        float x = head_w[h];
        float hw = ((x > 20.f) ? x : log1pf(__expf(x))) * HWF;

        float qv;
        if (e < 16)       qv = pr[h * 16 + e] * S1;
        else if (e < 28)  qv = s_qp3[h * 12 + (e - 16)] * hw;
        else if (e == 28) qv = -0.5f * hw;
        else if (e == 29) {
            float nq = 0.f;
            #pragma unroll
            for (int d = 0; d < 12; d++) { float v = s_qp3[h * 12 + d]; nq += v * v; }
            qv = -0.5f * hw * nq;
        } else qv = 0.f;
        g_qb[((size_t)h * NN + n) * 32 + e] = qv;

        if (e >= 16) {
            float kv2;
            if (e < 28)       kv2 = s_kp3[h * 12 + (e - 16)];
            else if (e == 28) {
                float nk = 0.f;
                #pragma unroll
                for (int d = 0; d < 12; d++) { float v = s_kp3[h * 12 + d]; nk += v * v; }
                kv2 = nk;
            }
            else if (e == 29) kv2 = 1.f;
            else              kv2 = 0.f;
            g_kb[((size_t)h * NN + n) * 32 + e] = kv2;
        }
    }
}

// ---------------- qkpts ----------------
__global__ __launch_bounds__(256) void qkpts_kernel(const float* __restrict__ mask)
{
    __shared__ float As[32][68];
    __shared__ float Bs[32][68];
    __shared__ float s_mi[64], s_mj[64];

    const int i0 = blockIdx.x * 64;
    const int j0 = blockIdx.y * 64;
    const int h  = blockIdx.z;
    const int t = threadIdx.x;

    #pragma unroll
    for (int r2 = 0; r2 < 2; r2++) {
        int li = t + r2 * 256;
        int row = li >> 3, c4 = (li & 7) * 4;
        float4 a = *(const float4*)&g_qb[((size_t)h * NN + i0 + row) * 32 + c4];
        As[c4 + 0][row] = a.x; As[c4 + 1][row] = a.y;
        As[c4 + 2][row] = a.z; As[c4 + 3][row] = a.w;
        float4 b = *(const float4*)&g_kb[((size_t)h * NN + j0 + row) * 32 + c4];
        Bs[c4 + 0][row] = b.x; Bs[c4 + 1][row] = b.y;
        Bs[c4 + 2][row] = b.z; Bs[c4 + 3][row] = b.w;
    }
    if (t < 64)              s_mi[t] = mask[i0 + t];
    else if (t < 128)        s_mj[t - 64] = mask[j0 + t - 64];
    __syncthreads();

    const int ty = t >> 4, tx = t & 15;
    float acc[4][4] = {};
    #pragma unroll
    for (int k = 0; k < 32; k++) {
        float4 a4 = *(const float4*)&As[k][ty * 4];
        float4 b4 = *(const float4*)&Bs[k][tx * 4];
        acc[0][0] += a4.x * b4.x; acc[0][1] += a4.x * b4.y; acc[0][2] += a4.x * b4.z; acc[0][3] += a4.x * b4.w;
        acc[1][0] += a4.y * b4.x; acc[1][1] += a4.y * b4.y; acc[1][2] += a4.y * b4.z; acc[1][3] += a4.y * b4.w;
        acc[2][0] += a4.z * b4.x; acc[2][1] += a4.z * b4.y; acc[2][2] += a4.z * b4.z; acc[2][3] += a4.z * b4.w;
        acc[3][0] += a4.w * b4.x; acc[3][1] += a4.w * b4.y; acc[3][2] += a4.w * b4.z; acc[3][3] += a4.w * b4.w;
    }
    #pragma unroll
    for (int rr = 0; rr < 4; rr++) {
        float mi = s_mi[ty * 4 + rr];
        float4 o;
        o.x = acc[rr][0] + 100000.f * (mi * s_mj[tx * 4 + 0] - 1.f);
        o.y = acc[rr][1] + 100000.f * (mi * s_mj[tx * 4 + 1] - 1.f);
        o.z = acc[rr][2] + 100000.f * (mi * s_mj[tx * 4 + 2] - 1.f);
        o.w = acc[rr][3] + 100000.f * (mi * s_mj[tx * 4 + 3] - 1.f);
        *(float4*)&g_qkp[(size_t)(i0 + ty * 4 + rr) * 9216 + h * 768 + j0 + tx * 4] = o;
    }
}

// ---------------- bias: tf32 MMA GEMM [589824 x 128] @ [128 x 12] ----------------
// Warp per 16-row tile. B (w_b) fragments prebuilt in registers (tile-invariant).
#define NTILES (NN * NN / 16)
__global__ __launch_bounds__(128) void bias_kernel(
    const float* __restrict__ z, const float* __restrict__ w_b,
    const float* __restrict__ b_b)
{
    const int t = threadIdx.x;
    const int lane = t & 31;
    const int tg = lane & 3;      // threadID_in_group
    const int gp = lane >> 2;     // groupID

    // B fragments for 16 k-steps, 2 n-tiles (cols 0-7, 8-15 with 12-15 zero)
    uint32_t B0[16][2], B1[16][2];
    #pragma unroll
    for (int kk = 0; kk < 16; kk++) {
        int k0 = kk * 8 + tg, k1 = k0 + 4;
        B0[kk][0] = to_tf32(w_b[k0 * 12 + gp]);
        B0[kk][1] = to_tf32(w_b[k1 * 12 + gp]);
        float w10 = (gp < 4) ? w_b[k0 * 12 + 8 + gp] : 0.f;
        float w11 = (gp < 4) ? w_b[k1 * 12 + 8 + gp] : 0.f;
        B1[kk][0] = to_tf32(w10);
        B1[kk][1] = to_tf32(w11);
    }
    const int cb = 2 * tg;
    const float bb0 = b_b[cb], bb1 = b_b[cb + 1];
    const float bb8 = (cb < 4) ? b_b[8 + cb] : 0.f;
    const float bb9 = (cb < 4) ? b_b[9 + cb] : 0.f;

    const int gw = (blockIdx.x * 128 + t) >> 5;
    const int nw = gridDim.x * 4;

    for (int tile = gw; tile < NTILES; tile += nw) {
        const float* zr = z + (size_t)tile * 16 * 128;
        float c0[4] = {0.f, 0.f, 0.f, 0.f};
        float c1[4] = {0.f, 0.f, 0.f, 0.f};

        #pragma unroll
        for (int kk = 0; kk < 16; kk++) {
            int co = kk * 8 + tg;
            uint32_t a0 = to_tf32(zr[gp * 128 + co]);
            uint32_t a1 = to_tf32(zr[(gp + 8) * 128 + co]);
            uint32_t a2 = to_tf32(zr[gp * 128 + co + 4]);
            uint32_t a3 = to_tf32(zr[(gp + 8) * 128 + co + 4]);
            mma_tf32(c0, a0, a1, a2, a3, B0[kk][0], B0[kk][1]);
            mma_tf32(c1, a0, a1, a2, a3, B1[kk][0], B1[kk][1]);
        }

        float* outr = g_bias + (size_t)tile * 16 * 12;
        // rows gp and gp+8, ntile0 cols cb,cb+1
        {
            float2 o;
            o.x = SQ13 * (c0[0] + bb0); o.y = SQ13 * (c0[1] + bb1);
            *(float2*)&outr[gp * 12 + cb] = o;
            o.x = SQ13 * (c0[2] + bb0); o.y = SQ13 * (c0[3] + bb1);
            *(float2*)&outr[(gp + 8) * 12 + cb] = o;
        }
        // ntile1 cols 8+cb, 9+cb (valid only tg<2)
        if (cb < 4) {
            float2 o;
            o.x = SQ13 * (c1[0] + bb8); o.y = SQ13 * (c1[1] + bb9);
            *(float2*)&outr[gp * 12 + 8 + cb] = o;
            o.x = SQ13 * (c1[2] + bb8); o.y = SQ13 * (c1[3] + bb9);
            *(float2*)&outr[(gp + 8) * 12 + 8 + cb] = o;
        }
    }
}

// ---------------- softmax: logits = qkp + bias; softmax per head; write a / aT ----------------
#define LP 772
__global__ __launch_bounds__(256) void softmax_kernel(const float* __restrict__ ss)
{
    __shared__ float s_l[12 * LP];
    __shared__ float s_w[768];

    const int i = blockIdx.x;
    const int t = threadIdx.x;

    for (int idx = t; idx < 9216; idx += 256) {
        int j = idx / 12, h = idx - j * 12;
        s_l[h * LP + j] = g_bias[(size_t)i * 9216 + idx];
    }
    for (int idx = t; idx < 768; idx += 256)
        s_w[idx] = __expf(ss[(size_t)i * 768 + idx]) - 0.99f;
    __syncthreads();
    for (int idx = t; idx < 9216; idx += 256) {
        int h = idx / 768, j = idx - h * 768;
        s_l[h * LP + j] += g_qkp[(size_t)i * 9216 + idx];
    }
    __syncthreads();

    const int wrp = t >> 5, lane = t & 31;
    for (int h = wrp; h < 12; h += 8) {
        float* lr = &s_l[h * LP];
        float m = -1e30f;
        for (int j = lane; j < 768; j += 32) m = fmaxf(m, lr[j]);
        #pragma unroll
        for (int o = 16; o; o >>= 1) m = fmaxf(m, __shfl_xor_sync(0xffffffffu, m, o));
        float sum = 0.f;
        for (int j = lane; j < 768; j += 32) {
            float p = __expf(lr[j] - m) * s_w[j];
            lr[j] = p;
            sum += p;
        }
        #pragma unroll
        for (int o = 16; o; o >>= 1) sum += __shfl_xor_sync(0xffffffffu, sum, o);
        float inv = 1.f / sum;
        for (int j = lane; j < 768; j += 32) lr[j] *= inv;
    }
    __syncthreads();

    for (int idx = t; idx < 9216; idx += 256) {
        int h = idx / 768, j = idx - h * 768;
        g_a[(size_t)i * 9216 + idx] = s_l[h * LP + j];
    }
    for (int idx = t; idx < 9216; idx += 256) {
        int j = idx / 12, h = idx - j * 12;
        g_aT[(size_t)i * 9216 + idx] = s_l[h * LP + j];
    }
}

// ---------------- opair: o_pair[i][h][c] = sum_j a[i][j][h]*z[i][j][c] ----------------
// 8 warps/block, a read via uniform LDG (L1-resident 36 KB/row-block), partials in smem.
#define OP_SMEM_FLOATS (8 * 12 * 128)
__global__ __launch_bounds__(256) void opair_kernel(const float* __restrict__ z)
{
    extern __shared__ float s_part[];   // [w][12][128]

    const int i = blockIdx.x;
    const int t = threadIdx.x;
    const int w = t >> 5, lane = t & 31;

    ull acc[6][4];
    #pragma unroll
    for (int q = 0; q < 6; q++)
        #pragma unroll
        for (int c = 0; c < 4; c++) acc[q][c] = 0ull;

    const float* zb = z + (size_t)i * 768 * 128 + lane * 4;
    const float* ab = g_aT + (size_t)i * 9216;

    for (int jb = w * 4; jb < 768; jb += 32) {
        float4 zv[4];
        float4 av[4][3];
        #pragma unroll
        for (int u = 0; u < 4; u++) {
            zv[u] = __ldg((const float4*)(zb + (size_t)(jb + u) * 128));
            av[u][0] = __ldg((const float4*)(ab + (jb + u) * 12));
            av[u][1] = __ldg((const float4*)(ab + (jb + u) * 12 + 4));
            av[u][2] = __ldg((const float4*)(ab + (jb + u) * 12 + 8));
        }
        #pragma unroll
        for (int u = 0; u < 4; u++) {
            ull ap[6];
            ap[0] = pack2(av[u][0].x, av[u][0].y);
            ap[1] = pack2(av[u][0].z, av[u][0].w);
            ap[2] = pack2(av[u][1].x, av[u][1].y);
            ap[3] = pack2(av[u][1].z, av[u][1].w);
            ap[4] = pack2(av[u][2].x, av[u][2].y);
            ap[5] = pack2(av[u][2].z, av[u][2].w);
            float zc[4] = {zv[u].x, zv[u].y, zv[u].z, zv[u].w};
            #pragma unroll
            for (int c = 0; c < 4; c++) {
                ull zz = pack2(zc[c], zc[c]);
                #pragma unroll
                for (int q = 0; q < 6; q++)
                    ffma2(acc[q][c], ap[q], zz);
            }
        }
    }

    #pragma unroll
    for (int q = 0; q < 6; q++) {
        #pragma unroll
        for (int c = 0; c < 4; c++) {
            float2 u = unpack2(acc[q][c]);
            s_part[(w * 12 + 2 * q + 0) * 128 + lane * 4 + c] = u.x;
            s_part[(w * 12 + 2 * q + 1) * 128 + lane * 4 + c] = u.y;
        }
    }
    __syncthreads();

    for (int idx = t; idx < 1536; idx += 256) {
        int h = idx >> 7, c = idx & 127;
        float s = 0.f;
        #pragma unroll
        for (int ww = 0; ww < 8; ww++)
            s += s_part[(ww * 12 + h) * 128 + c];
        g_feats[(size_t)i * FEAT_N + 576 + h * 128 + c] = s;
    }
}

// ---------------- ov: 32-row tiles, 128 threads, grid (24,12) ----------------
__global__ __launch_bounds__(128) void ov_kernel()
{
    __shared__ float s_a[32 * 64];
    __shared__ float s_v[64 * 40];

    const int i0 = blockIdx.x * 32;
    const int h  = blockIdx.y;
    const int t = threadIdx.x;
    const int ig = t >> 3;
    const int og = t & 7;

    float acc[2][5] = {};

    for (int j0 = 0; j0 < 768; j0 += 64) {
        #pragma unroll
        for (int it = 0; it < 4; it++) {
            int idx = t + it * 128;
            int row = idx >> 4, q = idx & 15;
            float4 av = *(const float4*)&g_a[((size_t)(i0 + row) * 12 + h) * 768 + j0 + q * 4];
            *(float4*)&s_a[row * 64 + q * 4] = av;
        }
        #pragma unroll
        for (int it = 0; it < 5; it++) {
            int idx = t + it * 128;
            int jj = idx / 10, q = idx - jj * 10;
            float4 vv = (q < 4)
                ? *(const float4*)&g_v[(j0 + jj) * 192 + h * 16 + q * 4]
                : *(const float4*)&g_vpts[(j0 + jj) * 288 + h * 24 + (q - 4) * 4];
            *(float4*)&s_v[jj * 40 + q * 4] = vv;
        }
        __syncthreads();
        #pragma unroll 8
        for (int jj = 0; jj < 64; jj++) {
            float a0 = s_a[(ig * 2 + 0) * 64 + jj];
            float a1 = s_a[(ig * 2 + 1) * 64 + jj];
            const float* vp = &s_v[jj * 40 + og * 5];
            #pragma unroll
            for (int u = 0; u < 5; u++) {
                float vv = vp[u];
                acc[0][u] += a0 * vv;
                acc[1][u] += a1 * vv;
            }
        }
        __syncthreads();
    }
    #pragma unroll
    for (int r = 0; r < 2; r++) {
        int n = i0 + ig * 2 + r;
        #pragma unroll
        for (int u = 0; u < 5; u++) {
            int e = og * 5 + u;
            if (e < 16) g_feats[(size_t)n * FEAT_N + h * 16 + e] = acc[r][u];
            else        g_optg[n * 288 + h * 24 + (e - 16)] = acc[r][u];
        }
    }
}

// ---------------- optfinal ----------------
__global__ __launch_bounds__(96) void optfinal_kernel(
    const float* __restrict__ rot, const float* __restrict__ trans)
{
    const int n = blockIdx.x;
    const int hp = threadIdx.x;
    float r[9], tr[3];
    #pragma unroll
    for (int e = 0; e < 9; e++) r[e] = rot[n * 9 + e];
    tr[0] = trans[n * 3 + 0]; tr[1] = trans[n * 3 + 1]; tr[2] = trans[n * 3 + 2];

    float gx = g_optg[n * 288 + hp * 3 + 0] - tr[0];
    float gy = g_optg[n * 288 + hp * 3 + 1] - tr[1];
    float gz = g_optg[n * 288 + hp * 3 + 2] - tr[2];
    float l0 = r[0] * gx + r[3] * gy + r[6] * gz;
    float l1 = r[1] * gx + r[4] * gy + r[7] * gz;
    float l2 = r[2] * gx + r[5] * gy + r[8] * gz;

    float* f = &g_feats[(size_t)n * FEAT_N];
    f[192 + hp] = l0;
    f[288 + hp] = l1;
    f[384 + hp] = l2;
    f[480 + hp] = sqrtf(l0 * l0 + l1 * l1 + l2 * l2 + 1e-8f);
}

// ---------------- launch ----------------
extern "C" void kernel_launch(void* const* d_in, const int* in_sizes, int n_in,
                              void* d_out, int out_size)
{
    const float* s       = (const float*)d_in[0];
    const float* z       = (const float*)d_in[1];
    const float* rot     = (const float*)d_in[2];
    const float* trans   = (const float*)d_in[3];
    const float* mask    = (const float*)d_in[4];
    const float* ss      = (const float*)d_in[5];
    const float* w_q     = (const float*)d_in[6];
    const float* b_q     = (const float*)d_in[7];
    const float* w_kv    = (const float*)d_in[8];
    const float* b_kv    = (const float*)d_in[9];
    const float* w_qp    = (const float*)d_in[10];
    const float* b_qp    = (const float*)d_in[11];
    const float* w_kvp   = (const float*)d_in[12];
    const float* b_kvp   = (const float*)d_in[13];
    const float* w_b     = (const float*)d_in[14];
    const float* b_b     = (const float*)d_in[15];
    const float* head_w  = (const float*)d_in[16];
    const float* w_out   = (const float*)d_in[17];
    const float* b_out   = (const float*)d_in[18];
    float* out = (float*)d_out;

    float* proj;  cudaGetSymbolAddress((void**)&proj, g_proj);
    float* feats; cudaGetSymbolAddress((void**)&feats, g_feats);

    static bool attr_done = false;
    if (!attr_done) {
        cudaFuncSetAttribute(opair_kernel,
                             cudaFuncAttributeMaxDynamicSharedMemorySize,
                             OP_SMEM_FLOATS * 4);
        attr_done = true;
    }

    // K1: projections (768 x 1152)
    gemm_kernel<<<dim3(18, 24), 256>>>(
        s, CS, w_q, w_kv, w_qp, w_kvp, b_q, b_kv, b_qp, b_kvp,
        192, 576, 720, 1152, proj, PROJ_N);

    // K2: split k/v, rotate points, build logit-GEMM rows
    prep_kernel<<<NN, 384>>>(rot, trans, head_w);

    // K2b: qk+pts+mask logits as 30-dim GEMM
    qkpts_kernel<<<dim3(12, 12, 12), 256>>>(mask);

    // K3a: z-bias via tf32 tensor-core MMA (z pass 1)
    bias_kernel<<<1184, 128>>>(z, w_b, b_b);

    // K3b: softmax
    softmax_kernel<<<NN, 256>>>(ss);

    // K3c: o_pair (z pass 2, 8 warps, MLP 16)
    opair_kernel<<<NN, 256, OP_SMEM_FLOATS * 4>>>(z);

    // K4: o and o_pt accumulation
    ov_kernel<<<dim3(24, 12), 128>>>();

    // K5: finalize o_pt + norms
    optfinal_kernel<<<NN, 96>>>(rot, trans);

    // K6: output GEMM (768 x 384, K=2112)
    gemm_kernel<<<dim3(6, 24), 256>>>(
        feats, FEAT_N, w_out, w_out, w_out, w_out, b_out, b_out, b_out, b_out,
        384, 384, 384, 384, out, CS);
}

// round 10
// speedup vs baseline: 1.2499x; 1.0798x over previous
#include <cuda_runtime.h>
#include <math.h>
#include <stdint.h>

#define NN 768
#define HH 12
#define CS 384
#define PROJ_N 1152
#define FEAT_N 2112   // [o 192 | ptx 96 | pty 96 | ptz 96 | ptnorm 96 | opair 1536]

typedef unsigned long long ull;

#define S1 0.14433756729740643f      // sqrt(1/48)
#define SQ13 0.5773502691896258f     // sqrt(1/3)
#define HWF 0.13608276348795434f     // sqrt(1/54)

__device__ __forceinline__ void ffma2(ull& d, ull a, ull b) {
    asm("fma.rn.f32x2 %0, %1, %2, %0;" : "+l"(d) : "l"(a), "l"(b));
}
__device__ __forceinline__ ull pack2(float x, float y) {
    ull r; asm("mov.b64 %0, {%1, %2};" : "=l"(r) : "f"(x), "f"(y)); return r;
}
__device__ __forceinline__ float2 unpack2(ull v) {
    float2 r; asm("mov.b64 {%0, %1}, %2;" : "=f"(r.x), "=f"(r.y) : "l"(v)); return r;
}
__device__ __forceinline__ uint32_t to_tf32(float f) {
    uint32_t r; asm("cvt.rna.tf32.f32 %0, %1;" : "=r"(r) : "f"(f)); return r;
}
__device__ __forceinline__ void mma_tf32(float c[4],
    uint32_t a0, uint32_t a1, uint32_t a2, uint32_t a3,
    uint32_t b0, uint32_t b1)
{
    asm("mma.sync.aligned.m16n8k8.row.col.f32.tf32.tf32.f32 "
        "{%0,%1,%2,%3}, {%4,%5,%6,%7}, {%8,%9}, {%0,%1,%2,%3};"
        : "+f"(c[0]), "+f"(c[1]), "+f"(c[2]), "+f"(c[3])
        : "r"(a0), "r"(a1), "r"(a2), "r"(a3), "r"(b0), "r"(b1));
}

// ---------------- scratch ----------------
__device__ float g_proj[NN * PROJ_N];
__device__ float g_v[NN * 192];
__device__ float g_vpts[NN * 288];
__device__ float g_qb[HH * NN * 32];
__device__ float g_kb[HH * NN * 32];
__device__ float g_qkp[(size_t)NN * HH * NN]; // [i][h][j]
__device__ float g_bias[(size_t)NN * NN * HH];// [i][j][h] = SQ13*(z@w_b + b_b)
__device__ float g_a[(size_t)NN * HH * NN];   // [i][h][j]
__device__ float g_aT[(size_t)NN * NN * HH];  // [i][j][h]
__device__ float g_optg[NN * 288];
__device__ float g_feats[NN * FEAT_N];

// ---------------- GEMM: out = A @ W + bias, segmented over N ----------------
__global__ __launch_bounds__(256) void gemm_kernel(
    const float* __restrict__ A, int K,
    const float* __restrict__ w0, const float* __restrict__ w1,
    const float* __restrict__ w2, const float* __restrict__ w3,
    const float* __restrict__ b0, const float* __restrict__ b1,
    const float* __restrict__ b2, const float* __restrict__ b3,
    int e0, int e1, int e2, int e3,
    float* __restrict__ out, int ldo)
{
    __shared__ float As[16][34];
    __shared__ float Bs[16][64];

    const int m0 = blockIdx.y * 32;
    const int n0 = blockIdx.x * 64;
    const int t = threadIdx.x;

    const int bkr = t >> 4;
    const int n   = n0 + (t & 15) * 4;
    const float* W; const float* bias; int base, segN;
    if (n < e0)      { W = w0; bias = b0; base = 0;  segN = e0; }
    else if (n < e1) { W = w1; bias = b1; base = e0; segN = e1 - e0; }
    else if (n < e2) { W = w2; bias = b2; base = e1; segN = e2 - e1; }
    else             { W = w3; bias = b3; base = e2; segN = e3 - e2; }

    const int ar  = t >> 2;
    const int ac4 = (t & 3) * 4;
    const int ty  = t >> 4;
    const int tx  = t & 15;

    float acc[2][4] = {};

    for (int k0 = 0; k0 < K; k0 += 16) {
        if (t < 128) {
            float4 av = *(const float4*)&A[(size_t)(m0 + ar) * K + k0 + ac4];
            As[ac4 + 0][ar] = av.x; As[ac4 + 1][ar] = av.y;
            As[ac4 + 2][ar] = av.z; As[ac4 + 3][ar] = av.w;
        }
        float4 bv = *(const float4*)&W[(size_t)(k0 + bkr) * segN + (n - base)];
        *(float4*)&Bs[bkr][(t & 15) * 4] = bv;
        __syncthreads();
        #pragma unroll
        for (int kk = 0; kk < 16; kk++) {
            float2 a2 = *(const float2*)&As[kk][ty * 2];
            float4 b4 = *(const float4*)&Bs[kk][tx * 4];
            acc[0][0] += a2.x * b4.x; acc[0][1] += a2.x * b4.y;
            acc[0][2] += a2.x * b4.z; acc[0][3] += a2.x * b4.w;
            acc[1][0] += a2.y * b4.x; acc[1][1] += a2.y * b4.y;
            acc[1][2] += a2.y * b4.z; acc[1][3] += a2.y * b4.w;
        }
        __syncthreads();
    }
    float4 bb = *(const float4*)&bias[n - base];
    #pragma unroll
    for (int r = 0; r < 2; r++) {
        float4 o;
        o.x = acc[r][0] + bb.x; o.y = acc[r][1] + bb.y;
        o.z = acc[r][2] + bb.z; o.w = acc[r][3] + bb.w;
        *(float4*)&out[(size_t)(m0 + ty * 2 + r) * ldo + n] = o;
    }
}

// ---------------- prep ----------------
__global__ __launch_bounds__(384) void prep_kernel(
    const float* __restrict__ rot, const float* __restrict__ trans,
    const float* __restrict__ head_w)
{
    __shared__ float s_qp3[144];
    __shared__ float s_kp3[144];

    const int n = blockIdx.x;
    const int t = threadIdx.x;
    const float* pr = &g_proj[(size_t)n * PROJ_N];

    if (t < 192) {
        int h = t >> 4, c = t & 15;
        g_kb[((size_t)h * NN + n) * 32 + c] = pr[192 + h * 32 + c];
        g_v[n * 192 + t] = pr[192 + h * 32 + 16 + c];
    }
    float r[9], tr[3];
    #pragma unroll
    for (int e = 0; e < 9; e++) r[e] = rot[n * 9 + e];
    tr[0] = trans[n * 3 + 0]; tr[1] = trans[n * 3 + 1]; tr[2] = trans[n * 3 + 2];

    if (t < 48) {
        float p0 = pr[576 + 0 * 48 + t];
        float p1 = pr[576 + 1 * 48 + t];
        float p2 = pr[576 + 2 * 48 + t];
        #pragma unroll
        for (int ii = 0; ii < 3; ii++)
            s_qp3[t * 3 + ii] = r[ii * 3 + 0] * p0 + r[ii * 3 + 1] * p1 + r[ii * 3 + 2] * p2 + tr[ii];
    }
    if (t >= 64 && t < 208) {
        int u = t - 64;
        float p0 = pr[720 + 0 * 144 + u];
        float p1 = pr[720 + 1 * 144 + u];
        float p2 = pr[720 + 2 * 144 + u];
        int h = u / 12, p = u % 12;
        #pragma unroll
        for (int ii = 0; ii < 3; ii++) {
            float o = r[ii * 3 + 0] * p0 + r[ii * 3 + 1] * p1 + r[ii * 3 + 2] * p2 + tr[ii];
            if (p < 4) s_kp3[(h * 4 + p) * 3 + ii] = o;
            else       g_vpts[n * 288 + (h * 8 + (p - 4)) * 3 + ii] = o;
        }
    }
    __syncthreads();

    {
        int h = t >> 5, e = t & 31;
        float x = head_w[h];
        float hw = ((x > 20.f) ? x : log1pf(__expf(x))) * HWF;

        float qv;
        if (e < 16)       qv = pr[h * 16 + e] * S1;
        else if (e < 28)  qv = s_qp3[h * 12 + (e - 16)] * hw;
        else if (e == 28) qv = -0.5f * hw;
        else if (e == 29) {
            float nq = 0.f;
            #pragma unroll
            for (int d = 0; d < 12; d++) { float v = s_qp3[h * 12 + d]; nq += v * v; }
            qv = -0.5f * hw * nq;
        } else qv = 0.f;
        g_qb[((size_t)h * NN + n) * 32 + e] = qv;

        if (e >= 16) {
            float kv2;
            if (e < 28)       kv2 = s_kp3[h * 12 + (e - 16)];
            else if (e == 28) {
                float nk = 0.f;
                #pragma unroll
                for (int d = 0; d < 12; d++) { float v = s_kp3[h * 12 + d]; nk += v * v; }
                kv2 = nk;
            }
            else if (e == 29) kv2 = 1.f;
            else              kv2 = 0.f;
            g_kb[((size_t)h * NN + n) * 32 + e] = kv2;
        }
    }
}

// ---------------- qkpts ----------------
__global__ __launch_bounds__(256) void qkpts_kernel(const float* __restrict__ mask)
{
    __shared__ float As[32][68];
    __shared__ float Bs[32][68];
    __shared__ float s_mi[64], s_mj[64];

    const int i0 = blockIdx.x * 64;
    const int j0 = blockIdx.y * 64;
    const int h  = blockIdx.z;
    const int t = threadIdx.x;

    #pragma unroll
    for (int r2 = 0; r2 < 2; r2++) {
        int li = t + r2 * 256;
        int row = li >> 3, c4 = (li & 7) * 4;
        float4 a = *(const float4*)&g_qb[((size_t)h * NN + i0 + row) * 32 + c4];
        As[c4 + 0][row] = a.x; As[c4 + 1][row] = a.y;
        As[c4 + 2][row] = a.z; As[c4 + 3][row] = a.w;
        float4 b = *(const float4*)&g_kb[((size_t)h * NN + j0 + row) * 32 + c4];
        Bs[c4 + 0][row] = b.x; Bs[c4 + 1][row] = b.y;
        Bs[c4 + 2][row] = b.z; Bs[c4 + 3][row] = b.w;
    }
    if (t < 64)              s_mi[t] = mask[i0 + t];
    else if (t < 128)        s_mj[t - 64] = mask[j0 + t - 64];
    __syncthreads();

    const int ty = t >> 4, tx = t & 15;
    float acc[4][4] = {};
    #pragma unroll
    for (int k = 0; k < 32; k++) {
        float4 a4 = *(const float4*)&As[k][ty * 4];
        float4 b4 = *(const float4*)&Bs[k][tx * 4];
        acc[0][0] += a4.x * b4.x; acc[0][1] += a4.x * b4.y; acc[0][2] += a4.x * b4.z; acc[0][3] += a4.x * b4.w;
        acc[1][0] += a4.y * b4.x; acc[1][1] += a4.y * b4.y; acc[1][2] += a4.y * b4.z; acc[1][3] += a4.y * b4.w;
        acc[2][0] += a4.z * b4.x; acc[2][1] += a4.z * b4.y; acc[2][2] += a4.z * b4.z; acc[2][3] += a4.z * b4.w;
        acc[3][0] += a4.w * b4.x; acc[3][1] += a4.w * b4.y; acc[3][2] += a4.w * b4.z; acc[3][3] += a4.w * b4.w;
    }
    #pragma unroll
    for (int rr = 0; rr < 4; rr++) {
        float mi = s_mi[ty * 4 + rr];
        float4 o;
        o.x = acc[rr][0] + 100000.f * (mi * s_mj[tx * 4 + 0] - 1.f);
        o.y = acc[rr][1] + 100000.f * (mi * s_mj[tx * 4 + 1] - 1.f);
        o.z = acc[rr][2] + 100000.f * (mi * s_mj[tx * 4 + 2] - 1.f);
        o.w = acc[rr][3] + 100000.f * (mi * s_mj[tx * 4 + 3] - 1.f);
        *(float4*)&g_qkp[(size_t)(i0 + ty * 4 + rr) * 9216 + h * 768 + j0 + tx * 4] = o;
    }
}

// ---------------- bias v2: smem-staged tf32 MMA GEMM [589824 x 128] @ [128 x 12] ----------------
// Block = 256 thr processes 128 rows/iter. z tile staged as tf32 bits (coalesced LDG.128),
// fragments fetched via conflict-free LDS (pitch 132). 8 warps x 16-row MMA tiles.
#define BT_TILES (NN * NN / 128)          // 4608
#define BS_SMEM_BYTES (128 * 132 * 4)     // 67584
__global__ __launch_bounds__(256, 2) void bias_kernel(
    const float* __restrict__ z, const float* __restrict__ w_b,
    const float* __restrict__ b_b)
{
    extern __shared__ uint32_t s_z[];     // [128][132] tf32 bits

    const int t = threadIdx.x;
    const int w = t >> 5;
    const int lane = t & 31;
    const int tg = lane & 3;      // threadID_in_group
    const int gp = lane >> 2;     // groupID

    // B fragments for 16 k-steps, 2 n-tiles (cols 0-7, 8-15 with 12-15 zero)
    uint32_t B0[16][2], B1[16][2];
    #pragma unroll
    for (int kk = 0; kk < 16; kk++) {
        int k0 = kk * 8 + tg, k1 = k0 + 4;
        B0[kk][0] = to_tf32(w_b[k0 * 12 + gp]);
        B0[kk][1] = to_tf32(w_b[k1 * 12 + gp]);
        float w10 = (gp < 4) ? w_b[k0 * 12 + 8 + gp] : 0.f;
        float w11 = (gp < 4) ? w_b[k1 * 12 + 8 + gp] : 0.f;
        B1[kk][0] = to_tf32(w10);
        B1[kk][1] = to_tf32(w11);
    }
    const int cb = 2 * tg;
    const float bb0 = b_b[cb], bb1 = b_b[cb + 1];
    const float bb8 = (cb < 4) ? b_b[8 + cb] : 0.f;
    const float bb9 = (cb < 4) ? b_b[9 + cb] : 0.f;

    const int col4 = lane * 4;    // staging column (0..124)
    const int rowg = w;           // staging row group

    for (int tile = blockIdx.x; tile < BT_TILES; tile += gridDim.x) {
        const float* zt = z + (size_t)tile * 128 * 128;
        __syncthreads();   // previous compute done before restage
        #pragma unroll
        for (int k = 0; k < 16; k++) {
            int row = rowg + k * 8;
            float4 v = __ldg((const float4*)(zt + row * 128 + col4));
            uint4 u;
            u.x = to_tf32(v.x); u.y = to_tf32(v.y);
            u.z = to_tf32(v.z); u.w = to_tf32(v.w);
            *(uint4*)&s_z[row * 132 + col4] = u;
        }
        __syncthreads();

        const uint32_t* sw = s_z + (w * 16) * 132;
        float c0[4] = {0.f, 0.f, 0.f, 0.f};
        float c1[4] = {0.f, 0.f, 0.f, 0.f};
        #pragma unroll
        for (int kk = 0; kk < 16; kk++) {
            int co = kk * 8 + tg;
            uint32_t a0 = sw[gp * 132 + co];
            uint32_t a1 = sw[(gp + 8) * 132 + co];
            uint32_t a2 = sw[gp * 132 + co + 4];
            uint32_t a3 = sw[(gp + 8) * 132 + co + 4];
            mma_tf32(c0, a0, a1, a2, a3, B0[kk][0], B0[kk][1]);
            mma_tf32(c1, a0, a1, a2, a3, B1[kk][0], B1[kk][1]);
        }

        float* outr = g_bias + ((size_t)tile * 128 + w * 16) * 12;
        {
            float2 o;
            o.x = SQ13 * (c0[0] + bb0); o.y = SQ13 * (c0[1] + bb1);
            *(float2*)&outr[gp * 12 + cb] = o;
            o.x = SQ13 * (c0[2] + bb0); o.y = SQ13 * (c0[3] + bb1);
            *(float2*)&outr[(gp + 8) * 12 + cb] = o;
        }
        if (cb < 4) {
            float2 o;
            o.x = SQ13 * (c1[0] + bb8); o.y = SQ13 * (c1[1] + bb9);
            *(float2*)&outr[gp * 12 + 8 + cb] = o;
            o.x = SQ13 * (c1[2] + bb8); o.y = SQ13 * (c1[3] + bb9);
            *(float2*)&outr[(gp + 8) * 12 + 8 + cb] = o;
        }
    }
}

// ---------------- softmax: logits = qkp + bias; softmax per head; write a / aT ----------------
#define LP 772
__global__ __launch_bounds__(256) void softmax_kernel(const float* __restrict__ ss)
{
    __shared__ float s_l[12 * LP];
    __shared__ float s_w[768];

    const int i = blockIdx.x;
    const int t = threadIdx.x;

    for (int idx = t; idx < 9216; idx += 256) {
        int j = idx / 12, h = idx - j * 12;
        s_l[h * LP + j] = g_bias[(size_t)i * 9216 + idx];
    }
    for (int idx = t; idx < 768; idx += 256)
        s_w[idx] = __expf(ss[(size_t)i * 768 + idx]) - 0.99f;
    __syncthreads();
    for (int idx = t; idx < 9216; idx += 256) {
        int h = idx / 768, j = idx - h * 768;
        s_l[h * LP + j] += g_qkp[(size_t)i * 9216 + idx];
    }
    __syncthreads();

    const int wrp = t >> 5, lane = t & 31;
    for (int h = wrp; h < 12; h += 8) {
        float* lr = &s_l[h * LP];
        float m = -1e30f;
        for (int j = lane; j < 768; j += 32) m = fmaxf(m, lr[j]);
        #pragma unroll
        for (int o = 16; o; o >>= 1) m = fmaxf(m, __shfl_xor_sync(0xffffffffu, m, o));
        float sum = 0.f;
        for (int j = lane; j < 768; j += 32) {
            float p = __expf(lr[j] - m) * s_w[j];
            lr[j] = p;
            sum += p;
        }
        #pragma unroll
        for (int o = 16; o; o >>= 1) sum += __shfl_xor_sync(0xffffffffu, sum, o);
        float inv = 1.f / sum;
        for (int j = lane; j < 768; j += 32) lr[j] *= inv;
    }
    __syncthreads();

    for (int idx = t; idx < 9216; idx += 256) {
        int h = idx / 768, j = idx - h * 768;
        g_a[(size_t)i * 9216 + idx] = s_l[h * LP + j];
    }
    for (int idx = t; idx < 9216; idx += 256) {
        int j = idx / 12, h = idx - j * 12;
        g_aT[(size_t)i * 9216 + idx] = s_l[h * LP + j];
    }
}

// ---------------- opair: o_pair[i][h][c] = sum_j a[i][j][h]*z[i][j][c] ----------------
#define OP_SMEM_FLOATS (8 * 12 * 128)
__global__ __launch_bounds__(256) void opair_kernel(const float* __restrict__ z)
{
    extern __shared__ float s_part[];   // [w][12][128]

    const int i = blockIdx.x;
    const int t = threadIdx.x;
    const int w = t >> 5, lane = t & 31;

    ull acc[6][4];
    #pragma unroll
    for (int q = 0; q < 6; q++)
        #pragma unroll
        for (int c = 0; c < 4; c++) acc[q][c] = 0ull;

    const float* zb = z + (size_t)i * 768 * 128 + lane * 4;
    const float* ab = g_aT + (size_t)i * 9216;

    for (int jb = w * 4; jb < 768; jb += 32) {
        float4 zv[4];
        float4 av[4][3];
        #pragma unroll
        for (int u = 0; u < 4; u++) {
            zv[u] = __ldg((const float4*)(zb + (size_t)(jb + u) * 128));
            av[u][0] = __ldg((const float4*)(ab + (jb + u) * 12));
            av[u][1] = __ldg((const float4*)(ab + (jb + u) * 12 + 4));
            av[u][2] = __ldg((const float4*)(ab + (jb + u) * 12 + 8));
        }
        #pragma unroll
        for (int u = 0; u < 4; u++) {
            ull ap[6];
            ap[0] = pack2(av[u][0].x, av[u][0].y);
            ap[1] = pack2(av[u][0].z, av[u][0].w);
            ap[2] = pack2(av[u][1].x, av[u][1].y);
            ap[3] = pack2(av[u][1].z, av[u][1].w);
            ap[4] = pack2(av[u][2].x, av[u][2].y);
            ap[5] = pack2(av[u][2].z, av[u][2].w);
            float zc[4] = {zv[u].x, zv[u].y, zv[u].z, zv[u].w};
            #pragma unroll
            for (int c = 0; c < 4; c++) {
                ull zz = pack2(zc[c], zc[c]);
                #pragma unroll
                for (int q = 0; q < 6; q++)
                    ffma2(acc[q][c], ap[q], zz);
            }
        }
    }

    #pragma unroll
    for (int q = 0; q < 6; q++) {
        #pragma unroll
        for (int c = 0; c < 4; c++) {
            float2 u = unpack2(acc[q][c]);
            s_part[(w * 12 + 2 * q + 0) * 128 + lane * 4 + c] = u.x;
            s_part[(w * 12 + 2 * q + 1) * 128 + lane * 4 + c] = u.y;
        }
    }
    __syncthreads();

    for (int idx = t; idx < 1536; idx += 256) {
        int h = idx >> 7, c = idx & 127;
        float s = 0.f;
        #pragma unroll
        for (int ww = 0; ww < 8; ww++)
            s += s_part[(ww * 12 + h) * 128 + c];
        g_feats[(size_t)i * FEAT_N + 576 + h * 128 + c] = s;
    }
}

// ---------------- ov: 32-row tiles, 128 threads, grid (24,12); s_a pitch 68 (bank-conflict-free) ----------------
__global__ __launch_bounds__(128) void ov_kernel()
{
    __shared__ float s_a[32 * 68];
    __shared__ float s_v[64 * 40];

    const int i0 = blockIdx.x * 32;
    const int h  = blockIdx.y;
    const int t = threadIdx.x;
    const int ig = t >> 3;
    const int og = t & 7;

    float acc[2][5] = {};

    for (int j0 = 0; j0 < 768; j0 += 64) {
        #pragma unroll
        for (int it = 0; it < 4; it++) {
            int idx = t + it * 128;
            int row = idx >> 4, q = idx & 15;
            float4 av = *(const float4*)&g_a[((size_t)(i0 + row) * 12 + h) * 768 + j0 + q * 4];
            *(float4*)&s_a[row * 68 + q * 4] = av;
        }
        #pragma unroll
        for (int it = 0; it < 5; it++) {
            int idx = t + it * 128;
            int jj = idx / 10, q = idx - jj * 10;
            float4 vv = (q < 4)
                ? *(const float4*)&g_v[(j0 + jj) * 192 + h * 16 + q * 4]
                : *(const float4*)&g_vpts[(j0 + jj) * 288 + h * 24 + (q - 4) * 4];
            *(float4*)&s_v[jj * 40 + q * 4] = vv;
        }
        __syncthreads();
        #pragma unroll 8
        for (int jj = 0; jj < 64; jj++) {
            float a0 = s_a[(ig * 2 + 0) * 68 + jj];
            float a1 = s_a[(ig * 2 + 1) * 68 + jj];
            const float* vp = &s_v[jj * 40 + og * 5];
            #pragma unroll
            for (int u = 0; u < 5; u++) {
                float vv = vp[u];
                acc[0][u] += a0 * vv;
                acc[1][u] += a1 * vv;
            }
        }
        __syncthreads();
    }
    #pragma unroll
    for (int r = 0; r < 2; r++) {
        int n = i0 + ig * 2 + r;
        #pragma unroll
        for (int u = 0; u < 5; u++) {
            int e = og * 5 + u;
            if (e < 16) g_feats[(size_t)n * FEAT_N + h * 16 + e] = acc[r][u];
            else        g_optg[n * 288 + h * 24 + (e - 16)] = acc[r][u];
        }
    }
}

// ---------------- optfinal ----------------
__global__ __launch_bounds__(96) void optfinal_kernel(
    const float* __restrict__ rot, const float* __restrict__ trans)
{
    const int n = blockIdx.x;
    const int hp = threadIdx.x;
    float r[9], tr[3];
    #pragma unroll
    for (int e = 0; e < 9; e++) r[e] = rot[n * 9 + e];
    tr[0] = trans[n * 3 + 0]; tr[1] = trans[n * 3 + 1]; tr[2] = trans[n * 3 + 2];

    float gx = g_optg[n * 288 + hp * 3 + 0] - tr[0];
    float gy = g_optg[n * 288 + hp * 3 + 1] - tr[1];
    float gz = g_optg[n * 288 + hp * 3 + 2] - tr[2];
    float l0 = r[0] * gx + r[3] * gy + r[6] * gz;
    float l1 = r[1] * gx + r[4] * gy + r[7] * gz;
    float l2 = r[2] * gx + r[5] * gy + r[8] * gz;

    float* f = &g_feats[(size_t)n * FEAT_N];
    f[192 + hp] = l0;
    f[288 + hp] = l1;
    f[384 + hp] = l2;
    f[480 + hp] = sqrtf(l0 * l0 + l1 * l1 + l2 * l2 + 1e-8f);
}

// ---------------- launch ----------------
extern "C" void kernel_launch(void* const* d_in, const int* in_sizes, int n_in,
                              void* d_out, int out_size)
{
    const float* s       = (const float*)d_in[0];
    const float* z       = (const float*)d_in[1];
    const float* rot     = (const float*)d_in[2];
    const float* trans   = (const float*)d_in[3];
    const float* mask    = (const float*)d_in[4];
    const float* ss      = (const float*)d_in[5];
    const float* w_q     = (const float*)d_in[6];
    const float* b_q     = (const float*)d_in[7];
    const float* w_kv    = (const float*)d_in[8];
    const float* b_kv    = (const float*)d_in[9];
    const float* w_qp    = (const float*)d_in[10];
    const float* b_qp    = (const float*)d_in[11];
    const float* w_kvp   = (const float*)d_in[12];
    const float* b_kvp   = (const float*)d_in[13];
    const float* w_b     = (const float*)d_in[14];
    const float* b_b     = (const float*)d_in[15];
    const float* head_w  = (const float*)d_in[16];
    const float* w_out   = (const float*)d_in[17];
    const float* b_out   = (const float*)d_in[18];
    float* out = (float*)d_out;

    float* proj;  cudaGetSymbolAddress((void**)&proj, g_proj);
    float* feats; cudaGetSymbolAddress((void**)&feats, g_feats);

    static bool attr_done = false;
    if (!attr_done) {
        cudaFuncSetAttribute(opair_kernel,
                             cudaFuncAttributeMaxDynamicSharedMemorySize,
                             OP_SMEM_FLOATS * 4);
        cudaFuncSetAttribute(bias_kernel,
                             cudaFuncAttributeMaxDynamicSharedMemorySize,
                             BS_SMEM_BYTES);
        attr_done = true;
    }

    // K1: projections (768 x 1152)
    gemm_kernel<<<dim3(18, 24), 256>>>(
        s, CS, w_q, w_kv, w_qp, w_kvp, b_q, b_kv, b_qp, b_kvp,
        192, 576, 720, 1152, proj, PROJ_N);

    // K2: split k/v, rotate points, build logit-GEMM rows
    prep_kernel<<<NN, 384>>>(rot, trans, head_w);

    // K2b: qk+pts+mask logits as 30-dim GEMM
    qkpts_kernel<<<dim3(12, 12, 12), 256>>>(mask);

    // K3a: z-bias via smem-staged tf32 MMA (z pass 1)
    bias_kernel<<<296, 256, BS_SMEM_BYTES>>>(z, w_b, b_b);

    // K3b: softmax
    softmax_kernel<<<NN, 256>>>(ss);

    // K3c: o_pair (z pass 2, 8 warps, MLP 16)
    opair_kernel<<<NN, 256, OP_SMEM_FLOATS * 4>>>(z);

    // K4: o and o_pt accumulation
    ov_kernel<<<dim3(24, 12), 128>>>();

    // K5: finalize o_pt + norms
    optfinal_kernel<<<NN, 96>>>(rot, trans);

    // K6: output GEMM (768 x 384, K=2112)
    gemm_kernel<<<dim3(6, 24), 256>>>(
        feats, FEAT_N, w_out, w_out, w_out, w_out, b_out, b_out, b_out, b_out,
        384, 384, 384, 384, out, CS);
}